// round 11
// baseline (speedup 1.0000x reference)
#include <cuda_runtime.h>
#include <cuda_fp16.h>
#include <cstdint>
#include <math.h>

// Problem constants
#define PIXELS 8192      // B*H*W = 8*32*32
#define DD 512
#define FF 32
#define NN 16384
#define HWSZ 1024
#define SPLITS 8
#define CPS (NN / SPLITS)   // 2048 codes per split
#define KS3 96              // 3 split blocks of 32 along K (fp16 2-term split)
#define NKT 6               // k16 steps
#define XSTR3 104           // x staging stride in halves (208B, conflict-free)
#define CH 128              // codes per double-buffered chunk

// Output layout (concatenated flattened outputs, float32):
#define OUT_OFF      0
#define CLOSEST_OFF  4194304
#define LOSS_OFF     4202496
#define PERP_OFF     4202497

// Scratch (no allocations allowed)
__device__ float g_xn[PIXELS * FF];       // normalized projected x, [p][32]
__device__ float g_en[NN * FF];           // normalized codebook, [n][32]
__device__ __half g_xsplit[PIXELS * KS3]; // linear [xh|xh|xm]
// g_esplit is FRAGMENT-ordered: [code-group of 8][kt 0..5][lane 0..31][4 fp16]
__device__ __half g_esplit[NN * KS3];
__device__ float g_pval[SPLITS * PIXELS]; // per-split best value
__device__ int   g_pidx[SPLITS * PIXELS]; // per-split best index
__device__ int   g_closest[PIXELS];
__device__ int   g_hist[NN];
__device__ float g_lossp[PIXELS];

// fp32 -> fp16 x2 split (hi 11 bits + mid 11 bits)
__device__ __forceinline__ void split2h(float v, __half& h0, __half& h1)
{
    h0 = __float2half_rn(v);
    float r1 = v - __half2float(h0);
    h1 = __float2half_rn(r1);
}

// ---------------------------------------------------------------------------
// Kernel A: 1x1 conv projection + channel L2 normalize + linear split layout.
// ---------------------------------------------------------------------------
__global__ void proj_norm_kernel(const float* __restrict__ enc,
                                 const float* __restrict__ pw,
                                 const float* __restrict__ pb)
{
    extern __shared__ float sm[];
    float* Ws  = sm;                 // 32*512
    float* xsh = sm + FF * DD;       // 32*33 (padded)
    float* nrm = xsh + 32 * 33;      // 32

    int tid = threadIdx.x;

    const float4* W4 = (const float4*)pw;
    float4* Ws4 = (float4*)Ws;
#pragma unroll
    for (int i = 0; i < 16; i++) Ws4[tid + 256 * i] = W4[tid + 256 * i];
    __syncthreads();

    int lane = tid & 31;     // pixel within tile
    int fg   = tid >> 5;     // 0..7
    int f0   = fg * 4;
    int p    = blockIdx.x * 32 + lane;
    int b    = p >> 10;
    int hw   = p & 1023;

    const float* ep = enc + (size_t)b * DD * HWSZ + hw;
    const float4* w0 = (const float4*)(Ws + (size_t)(f0 + 0) * DD);
    const float4* w1 = (const float4*)(Ws + (size_t)(f0 + 1) * DD);
    const float4* w2 = (const float4*)(Ws + (size_t)(f0 + 2) * DD);
    const float4* w3 = (const float4*)(Ws + (size_t)(f0 + 3) * DD);

    float a0 = 0.f, a1 = 0.f, a2 = 0.f, a3 = 0.f;
#pragma unroll 4
    for (int q = 0; q < 128; q++) {
        float e0 = ep[(4 * q + 0) * HWSZ];
        float e1 = ep[(4 * q + 1) * HWSZ];
        float e2 = ep[(4 * q + 2) * HWSZ];
        float e3 = ep[(4 * q + 3) * HWSZ];
        float4 W0 = w0[q], W1 = w1[q], W2 = w2[q], W3 = w3[q];
        a0 += e0 * W0.x; a0 += e1 * W0.y; a0 += e2 * W0.z; a0 += e3 * W0.w;
        a1 += e0 * W1.x; a1 += e1 * W1.y; a1 += e2 * W1.z; a1 += e3 * W1.w;
        a2 += e0 * W2.x; a2 += e1 * W2.y; a2 += e2 * W2.z; a2 += e3 * W2.w;
        a3 += e0 * W3.x; a3 += e1 * W3.y; a3 += e2 * W3.z; a3 += e3 * W3.w;
    }
    a0 += pb[f0 + 0];
    a1 += pb[f0 + 1];
    a2 += pb[f0 + 2];
    a3 += pb[f0 + 3];

    xsh[lane * 33 + f0 + 0] = a0;
    xsh[lane * 33 + f0 + 1] = a1;
    xsh[lane * 33 + f0 + 2] = a2;
    xsh[lane * 33 + f0 + 3] = a3;
    __syncthreads();

    if (tid < 32) {
        float ss = 0.f;
#pragma unroll
        for (int f = 0; f < 32; f++) { float v = xsh[tid * 33 + f]; ss += v * v; }
        nrm[tid] = fmaxf(sqrtf(ss), 1e-6f);
    }
    __syncthreads();

    float nm = nrm[lane];
    float o[4] = { a0 / nm, a1 / nm, a2 / nm, a3 / nm };
    *(float4*)(g_xn + (size_t)p * FF + f0) = *(float4*)o;

    // X split blocks (linear): [xh | xh | xm]
    __half* xr = g_xsplit + (size_t)p * KS3;
#pragma unroll
    for (int k = 0; k < 4; k++) {
        __half h, m;
        split2h(o[k], h, m);
        int f = f0 + k;
        xr[f]       = h;
        xr[32 + f]  = h;
        xr[64 + f]  = m;
    }
}

// ---------------------------------------------------------------------------
// Kernel B: codebook L2 normalize + FRAGMENT-ordered split store.
// ---------------------------------------------------------------------------
__device__ __forceinline__ void efrag_store(int r, int k_eff, __half v)
{
    int kt  = k_eff >> 4;
    int kr  = k_eff & 15;
    int fl  = (r & 7) * 4 + ((kr & 7) >> 1);
    int el  = (kr >> 3) * 2 + (kr & 1);
    g_esplit[(size_t)(r >> 3) * (NKT * 128) + kt * 128 + fl * 4 + el] = v;
}

__global__ void enorm_kernel(const float* __restrict__ emb)
{
    int tid  = threadIdx.x;
    int r    = blockIdx.x * 8 + (tid >> 5);
    int lane = tid & 31;
    float v = emb[(size_t)r * 32 + lane];
    float ss = v * v;
#pragma unroll
    for (int o = 16; o; o >>= 1) ss += __shfl_xor_sync(0xffffffffu, ss, o);
    float nm = fmaxf(sqrtf(ss), 1e-6f);
    float en = v / nm;
    g_en[(size_t)r * 32 + lane] = en;

    __half h, m;
    split2h(en, h, m);
    efrag_store(r, lane, h);
    efrag_store(r, 32 + lane, m);
    efrag_store(r, 64 + lane, h);
}

// ---------------------------------------------------------------------------
// Kernel H: zero histogram (keeps sims in ncu's captured launch slot)
// ---------------------------------------------------------------------------
__global__ void histzero_kernel()
{
    g_hist[blockIdx.x * 256 + threadIdx.x] = 0;
}

// ---------------------------------------------------------------------------
// mma.sync m16n8k16 row.col fp16 -> f32
// ---------------------------------------------------------------------------
__device__ __forceinline__ void mma16816h(float* c, const uint32_t* a,
                                          uint32_t b0, uint32_t b1)
{
    asm volatile(
        "mma.sync.aligned.m16n8k16.row.col.f32.f16.f16.f32 "
        "{%0,%1,%2,%3}, {%4,%5,%6,%7}, {%8,%9}, {%0,%1,%2,%3};"
        : "+f"(c[0]), "+f"(c[1]), "+f"(c[2]), "+f"(c[3])
        : "r"(a[0]), "r"(a[1]), "r"(a[2]), "r"(a[3]), "r"(b0), "r"(b1));
}

__device__ __forceinline__ uint32_t smem_u32c(const void* p) {
    uint32_t a;
    asm("{ .reg .u64 t; cvta.to.shared.u64 t, %1; cvt.u32.u64 %0, t; }"
        : "=r"(a) : "l"(p));
    return a;
}

// ---------------------------------------------------------------------------
// Kernel C (dominant): fp16 3-term split cosine sims on tensor cores.
// Argmax hot path: 7-op fmaxf tree + 1 compare; index recovery only on the
// rare record-breaking improvement (ln(n) expected occurrences).
// ---------------------------------------------------------------------------
__global__ void __launch_bounds__(256, 2) sims_argmax_kernel()
{
    extern __shared__ __half smc[];  // 51200B: staging then 2x24576B bufs + merge

    int tid  = threadIdx.x;
    int wid  = tid >> 5;
    int lane = tid & 31;
    int g    = lane >> 2;   // row group / B column
    int kq   = lane & 3;    // k quad
    int cw   = wid >> 2;    // code half of the 128-chunk (0/1)
    int mw   = wid & 3;     // pixel quarter (32 px each)
    int px0  = blockIdx.x * 128;
    int cbase = blockIdx.y * CPS;

    // stage x tile linear: 128 rows x 12 uint4 (192B/row), stride XSTR3 halves
    for (int i = tid; i < 128 * 12; i += 256) {
        int r = i / 12, q = i % 12;
        ((uint4*)(smc + r * XSTR3))[q] =
            ((const uint4*)(g_xsplit + (size_t)(px0 + r) * KS3))[q];
    }
    __syncthreads();

    // extract A fragments once: A[kt][mt][4], held in registers throughout
    uint32_t A[NKT][2][4];
#pragma unroll
    for (int kt = 0; kt < NKT; kt++) {
        int k0 = kt * 16 + kq * 2;
#pragma unroll
        for (int mt = 0; mt < 2; mt++) {
            int r0 = mw * 32 + mt * 16 + g;
            A[kt][mt][0] = *(const uint32_t*)(smc + r0 * XSTR3 + k0);
            A[kt][mt][1] = *(const uint32_t*)(smc + (r0 + 8) * XSTR3 + k0);
            A[kt][mt][2] = *(const uint32_t*)(smc + r0 * XSTR3 + k0 + 8);
            A[kt][mt][3] = *(const uint32_t*)(smc + (r0 + 8) * XSTR3 + k0 + 8);
        }
    }
    __syncthreads();   // staging dead; reuse as double buffers

    uint32_t buf_base = smem_u32c(smc);     // buf0 @ +0, buf1 @ +24576 bytes
    const int CHB = CH * KS3 * 2;           // 24576 bytes per chunk

    // preload chunk 0 into buf0 (each thread copies 6x16B)
    {
        const char* src = (const char*)(g_esplit + (size_t)cbase * KS3);
#pragma unroll
        for (int j = 0; j < 6; j++) {
            uint32_t d = buf_base + (tid + 256 * j) * 16;
            asm volatile("cp.async.ca.shared.global [%0], [%1], 16;"
                         :: "r"(d), "l"(src + (tid + 256 * j) * 16) : "memory");
        }
        asm volatile("cp.async.commit_group;" ::: "memory");
    }

    float bv[4];
    int   bi[4];
#pragma unroll
    for (int s = 0; s < 4; s++) { bv[s] = -3.4e38f; bi[s] = 0; }

    for (int ch = 0; ch < CPS; ch += CH) {
        int cur = (ch >> 7) & 1;
        __syncthreads();   // prev chunk fully consumed before overwrite
        if (ch + CH < CPS) {
            const char* src = (const char*)(g_esplit + (size_t)(cbase + ch + CH) * KS3);
            uint32_t dbase = buf_base + (cur ^ 1) * CHB;
#pragma unroll
            for (int j = 0; j < 6; j++) {
                uint32_t d = dbase + (tid + 256 * j) * 16;
                asm volatile("cp.async.ca.shared.global [%0], [%1], 16;"
                             :: "r"(d), "l"(src + (tid + 256 * j) * 16) : "memory");
            }
            asm volatile("cp.async.commit_group;" ::: "memory");
            asm volatile("cp.async.wait_group 1;" ::: "memory");
        } else {
            asm volatile("cp.async.wait_group 0;" ::: "memory");
        }
        __syncthreads();   // chunk cur visible

        const char* ebuf = (const char*)smc + cur * CHB;

#pragma unroll
        for (int sub = 0; sub < 2; sub++) {
            const char* es = ebuf + (cw * 8 + sub * 4) * (NKT * 256);

            float acc[4][2][4];
#pragma unroll
            for (int nt = 0; nt < 4; nt++)
#pragma unroll
                for (int mt = 0; mt < 2; mt++)
#pragma unroll
                    for (int c = 0; c < 4; c++) acc[nt][mt][c] = 0.f;

#pragma unroll
            for (int kt = 0; kt < NKT; kt++) {
#pragma unroll
                for (int nt = 0; nt < 4; nt++) {
                    uint2 bb = *(const uint2*)(es + nt * (NKT * 256)
                                               + kt * 256 + lane * 8);
                    mma16816h(acc[nt][0], A[kt][0], bb.x, bb.y);
                    mma16816h(acc[nt][1], A[kt][1], bb.x, bb.y);
                }
            }

            // cheap argmax: fmaxf tree (branch-free) + rare index recovery.
            // Recovery scans DESCENDING so the final overwrite is the LOWEST
            // matching code index (first occurrence, jnp.argmax semantics);
            // strict > vs bv keeps earlier chunks' priority.
            int base = cbase + ch + cw * 64 + sub * 32 + kq * 2;
#pragma unroll
            for (int mt = 0; mt < 2; mt++) {
#pragma unroll
                for (int h = 0; h < 2; h++) {
                    int s = mt * 2 + h;
                    float m01 = fmaxf(acc[0][mt][h * 2], acc[0][mt][h * 2 + 1]);
                    float m23 = fmaxf(acc[1][mt][h * 2], acc[1][mt][h * 2 + 1]);
                    float m45 = fmaxf(acc[2][mt][h * 2], acc[2][mt][h * 2 + 1]);
                    float m67 = fmaxf(acc[3][mt][h * 2], acc[3][mt][h * 2 + 1]);
                    float vm = fmaxf(fmaxf(m01, m23), fmaxf(m45, m67));
                    if (vm > bv[s]) {
                        bv[s] = vm;
                        int idx = 0;
#pragma unroll
                        for (int nt = 3; nt >= 0; nt--) {
                            if (acc[nt][mt][h * 2 + 1] == vm) idx = base + nt * 8 + 1;
                            if (acc[nt][mt][h * 2 + 0] == vm) idx = base + nt * 8;
                        }
                        bi[s] = idx;
                    }
                }
            }
        }
    }

    // reduce across the 4 kq lanes (lower index wins ties)
#pragma unroll
    for (int s = 0; s < 4; s++) {
#pragma unroll
        for (int o = 1; o <= 2; o <<= 1) {
            float ov = __shfl_xor_sync(0xffffffffu, bv[s], o);
            int   oi = __shfl_xor_sync(0xffffffffu, bi[s], o);
            if (ov > bv[s] || (ov == bv[s] && oi < bi[s])) { bv[s] = ov; bi[s] = oi; }
        }
    }

    // merge the two code-half warps per pixel via smem (bytes 49152..51200)
    float* sv = (float*)((char*)smc + 49152);   // [2][128]
    int*   si = (int*)(sv + 256);               // [2][128]
    __syncthreads();
    if (kq == 0) {
#pragma unroll
        for (int s = 0; s < 4; s++) {
            int mt = s >> 1, h = s & 1;
            int pix = mw * 32 + mt * 16 + h * 8 + g;
            sv[cw * 128 + pix] = bv[s];
            si[cw * 128 + pix] = bi[s];
        }
    }
    __syncthreads();
    if (tid < 128) {
        float v0 = sv[tid];       int i0 = si[tid];
        float v1 = sv[128 + tid]; int i1 = si[128 + tid];
        if (v1 > v0 || (v1 == v0 && i1 < i0)) { v0 = v1; i0 = i1; }
        g_pval[blockIdx.y * PIXELS + px0 + tid] = v0;
        g_pidx[blockIdx.y * PIXELS + px0 + tid] = i0;
    }
}

// ---------------------------------------------------------------------------
// Kernel F: reduce split partials -> closest; histogram; per-pixel loss partial.
// ---------------------------------------------------------------------------
__global__ void reduce_kernel(float* __restrict__ out)
{
    int p = blockIdx.x * 256 + threadIdx.x;
    float bv = -3.4e38f;
    int   bi = 0x7fffffff;
#pragma unroll
    for (int s = 0; s < SPLITS; s++) {
        float v = g_pval[s * PIXELS + p];
        int  ix = g_pidx[s * PIXELS + p];
        if (v > bv || (v == bv && ix < bi)) { bv = v; bi = ix; }
    }
    g_closest[p] = bi;
    out[CLOSEST_OFF + p] = (float)bi;
    atomicAdd(&g_hist[bi], 1);

    float s2 = 0.f;
    const float4* xr = (const float4*)(g_xn + (size_t)p * 32);
    const float4* er = (const float4*)(g_en + (size_t)bi * 32);
#pragma unroll
    for (int q = 0; q < 8; q++) {
        float4 x = xr[q], e = er[q];
        float d0 = x.x - e.x, d1 = x.y - e.y, d2 = x.z - e.z, d3 = x.w - e.w;
        s2 += d0 * d0; s2 += d1 * d1; s2 += d2 * d2; s2 += d3 * d3;
    }
    g_lossp[p] = s2;
}

// ---------------------------------------------------------------------------
// Kernel D: expansion GEMM: out[b,d,hw] = sum_f lat[p][f] * exp_w[d][f] + exp_b[d]
// ---------------------------------------------------------------------------
__global__ void expand_kernel(const float* __restrict__ ew,
                              const float* __restrict__ eb,
                              float* __restrict__ out)
{
    __shared__ float Wsh[64 * 32];
    __shared__ float bsh[64];
    int tid = threadIdx.x;
    int d0  = blockIdx.y * 64;

    const float4* src = (const float4*)(ew + (size_t)d0 * 32);
    float4* dst = (float4*)Wsh;
    dst[tid]       = src[tid];
    dst[tid + 256] = src[tid + 256];
    if (tid < 64) bsh[tid] = eb[d0 + tid];
    __syncthreads();

    int p  = blockIdx.x * 256 + tid;
    int b  = p >> 10;
    int hw = p & 1023;
    int idx = g_closest[p];

    float4 lat[8];
    const float4* lr = (const float4*)(g_en + (size_t)idx * 32);
#pragma unroll
    for (int q = 0; q < 8; q++) lat[q] = lr[q];

    float* outp = out + OUT_OFF + ((size_t)b * 512 + d0) * 1024 + hw;
#pragma unroll 2
    for (int dd = 0; dd < 64; dd++) {
        const float4* wr = (const float4*)(Wsh + dd * 32);
        float s = bsh[dd];
#pragma unroll
        for (int q = 0; q < 8; q++) {
            float4 w = wr[q];
            s += lat[q].x * w.x; s += lat[q].y * w.y;
            s += lat[q].z * w.z; s += lat[q].w * w.w;
        }
        outp[(size_t)dd * 1024] = s;
    }
}

// ---------------------------------------------------------------------------
// Kernel G: deterministic final reductions -> loss_q, perplexity
// ---------------------------------------------------------------------------
__global__ void finalize_kernel(float* __restrict__ out)
{
    __shared__ double sh[256];
    int tid = threadIdx.x;

    double ls = 0.0;
    for (int i = tid; i < PIXELS; i += 256) ls += (double)g_lossp[i];
    sh[tid] = ls;
    __syncthreads();
    for (int o = 128; o; o >>= 1) {
        if (tid < o) sh[tid] += sh[tid + o];
        __syncthreads();
    }
    double loss = sh[0] / (double)(PIXELS * 32);
    __syncthreads();

    double ps = 0.0;
    for (int i = tid; i < NN; i += 256) {
        float u = (float)g_hist[i] * (1.0f / 8192.0f);
        ps += -(double)u * log((double)u + 1e-6);
    }
    sh[tid] = ps;
    __syncthreads();
    for (int o = 128; o; o >>= 1) {
        if (tid < o) sh[tid] += sh[tid + o];
        __syncthreads();
    }
    if (tid == 0) {
        out[LOSS_OFF] = (float)loss;
        out[PERP_OFF] = (float)exp(sh[0]);
    }
}

// ---------------------------------------------------------------------------
extern "C" void kernel_launch(void* const* d_in, const int* in_sizes, int n_in,
                              void* d_out, int out_size)
{
    const float* enc = (const float*)d_in[0];  // [8,512,32,32]
    const float* emb = (const float*)d_in[1];  // [16384,32]
    const float* pw  = (const float*)d_in[2];  // [32,512]
    const float* pb  = (const float*)d_in[3];  // [32]
    const float* ew  = (const float*)d_in[4];  // [512,32]
    const float* eb  = (const float*)d_in[5];  // [512]
    float* out = (float*)d_out;

    (void)in_sizes; (void)n_in; (void)out_size;

    const int a_smem = (FF * DD + 32 * 33 + 32) * (int)sizeof(float); // 69888
    cudaFuncSetAttribute(proj_norm_kernel,
                         cudaFuncAttributeMaxDynamicSharedMemorySize, a_smem);

    const int c_smem = 51200;  // 2x24576 chunk buffers + 2048 merge
    cudaFuncSetAttribute(sims_argmax_kernel,
                         cudaFuncAttributeMaxDynamicSharedMemorySize, c_smem);

    proj_norm_kernel<<<256, 256, a_smem>>>(enc, pw, pb);
    enorm_kernel<<<2048, 256>>>(emb);
    histzero_kernel<<<64, 256>>>();
    sims_argmax_kernel<<<dim3(64, SPLITS), 256, c_smem>>>();
    reduce_kernel<<<32, 256>>>(out);
    expand_kernel<<<dim3(32, 8), 256>>>(ew, eb, out);
    finalize_kernel<<<1, 256>>>(out);
}

// round 12
// speedup vs baseline: 1.0172x; 1.0172x over previous
#include <cuda_runtime.h>
#include <cuda_fp16.h>
#include <cstdint>
#include <math.h>

// Problem constants
#define PIXELS 8192      // B*H*W = 8*32*32
#define DD 512
#define FF 32
#define NN 16384
#define HWSZ 1024
#define SPLITS 8
#define CPS (NN / SPLITS)   // 2048 codes per split
#define CH2 256             // codes per double-buffered chunk (stage kernels)
#define XH_STR 40           // x-hi staging stride in halves (80B rows)
#define DELTA 2.5e-3f       // screening margin >= 2 * |true - hi.hi| bound

// Output layout (concatenated flattened outputs, float32):
#define OUT_OFF      0
#define CLOSEST_OFF  4194304
#define LOSS_OFF     4202496
#define PERP_OFF     4202497

// Scratch (no allocations allowed)
__device__ float g_xn[PIXELS * FF];       // normalized projected x, [p][32]
__device__ float g_en[NN * FF];           // normalized codebook, [n][32]
__device__ __half g_xhi[PIXELS * FF];     // fp16(xn), linear [p][32]
// g_ehi FRAGMENT-ordered: [code-group of 8][kt 0..1][lane 0..31][4 fp16]
__device__ __half g_ehi[NN * FF];
__device__ float g_pval[SPLITS * PIXELS]; // per-split best (stage1: approx, stage2: true)
__device__ int   g_pidx[SPLITS * PIXELS]; // per-split best index (stage2)
__device__ float g_amax[PIXELS];          // global approx max per pixel
__device__ int   g_closest[PIXELS];
__device__ int   g_hist[NN];
__device__ float g_lossp[PIXELS];

// ---------------------------------------------------------------------------
// Kernel A: 1x1 conv projection + channel L2 normalize + fp16 hi copy.
// ---------------------------------------------------------------------------
__global__ void proj_norm_kernel(const float* __restrict__ enc,
                                 const float* __restrict__ pw,
                                 const float* __restrict__ pb)
{
    extern __shared__ float sm[];
    float* Ws  = sm;                 // 32*512
    float* xsh = sm + FF * DD;       // 32*33 (padded)
    float* nrm = xsh + 32 * 33;      // 32

    int tid = threadIdx.x;

    const float4* W4 = (const float4*)pw;
    float4* Ws4 = (float4*)Ws;
#pragma unroll
    for (int i = 0; i < 16; i++) Ws4[tid + 256 * i] = W4[tid + 256 * i];
    __syncthreads();

    int lane = tid & 31;     // pixel within tile
    int fg   = tid >> 5;     // 0..7
    int f0   = fg * 4;
    int p    = blockIdx.x * 32 + lane;
    int b    = p >> 10;
    int hw   = p & 1023;

    const float* ep = enc + (size_t)b * DD * HWSZ + hw;
    const float4* w0 = (const float4*)(Ws + (size_t)(f0 + 0) * DD);
    const float4* w1 = (const float4*)(Ws + (size_t)(f0 + 1) * DD);
    const float4* w2 = (const float4*)(Ws + (size_t)(f0 + 2) * DD);
    const float4* w3 = (const float4*)(Ws + (size_t)(f0 + 3) * DD);

    float a0 = 0.f, a1 = 0.f, a2 = 0.f, a3 = 0.f;
#pragma unroll 4
    for (int q = 0; q < 128; q++) {
        float e0 = ep[(4 * q + 0) * HWSZ];
        float e1 = ep[(4 * q + 1) * HWSZ];
        float e2 = ep[(4 * q + 2) * HWSZ];
        float e3 = ep[(4 * q + 3) * HWSZ];
        float4 W0 = w0[q], W1 = w1[q], W2 = w2[q], W3 = w3[q];
        a0 += e0 * W0.x; a0 += e1 * W0.y; a0 += e2 * W0.z; a0 += e3 * W0.w;
        a1 += e0 * W1.x; a1 += e1 * W1.y; a1 += e2 * W1.z; a1 += e3 * W1.w;
        a2 += e0 * W2.x; a2 += e1 * W2.y; a2 += e2 * W2.z; a2 += e3 * W2.w;
        a3 += e0 * W3.x; a3 += e1 * W3.y; a3 += e2 * W3.z; a3 += e3 * W3.w;
    }
    a0 += pb[f0 + 0];
    a1 += pb[f0 + 1];
    a2 += pb[f0 + 2];
    a3 += pb[f0 + 3];

    xsh[lane * 33 + f0 + 0] = a0;
    xsh[lane * 33 + f0 + 1] = a1;
    xsh[lane * 33 + f0 + 2] = a2;
    xsh[lane * 33 + f0 + 3] = a3;
    __syncthreads();

    if (tid < 32) {
        float ss = 0.f;
#pragma unroll
        for (int f = 0; f < 32; f++) { float v = xsh[tid * 33 + f]; ss += v * v; }
        nrm[tid] = fmaxf(sqrtf(ss), 1e-6f);
    }
    __syncthreads();

    float nm = nrm[lane];
    float o[4] = { a0 / nm, a1 / nm, a2 / nm, a3 / nm };
    *(float4*)(g_xn + (size_t)p * FF + f0) = *(float4*)o;

    __half* xr = g_xhi + (size_t)p * FF;
#pragma unroll
    for (int k = 0; k < 4; k++)
        xr[f0 + k] = __float2half_rn(o[k]);
}

// ---------------------------------------------------------------------------
// Kernel B: codebook L2 normalize + fragment-ordered fp16 hi store + histzero.
// ---------------------------------------------------------------------------
__global__ void enorm_kernel(const float* __restrict__ emb)
{
    int tid  = threadIdx.x;
    int r    = blockIdx.x * 8 + (tid >> 5);
    int lane = tid & 31;
    float v = emb[(size_t)r * 32 + lane];
    float ss = v * v;
#pragma unroll
    for (int o = 16; o; o >>= 1) ss += __shfl_xor_sync(0xffffffffu, ss, o);
    float nm = fmaxf(sqrtf(ss), 1e-6f);
    float en = v / nm;
    g_en[(size_t)r * 32 + lane] = en;

    // fragment order: [group=r>>3][kt=k>>4][fl=(r&7)*4+((k&7)>>1)][el=((k&15)>>3)*2+(k&1)]
    int k  = lane;
    int kt = k >> 4;
    int kr = k & 15;
    int fl = (r & 7) * 4 + ((kr & 7) >> 1);
    int el = (kr >> 3) * 2 + (kr & 1);
    g_ehi[(size_t)(r >> 3) * 256 + kt * 128 + fl * 4 + el] = __float2half_rn(en);

    if (tid < 8) g_hist[blockIdx.x * 8 + tid] = 0;
}

// ---------------------------------------------------------------------------
// mma.sync m16n8k16 row.col fp16 -> f32
// ---------------------------------------------------------------------------
__device__ __forceinline__ void mma16816h(float* c, const uint32_t* a,
                                          uint32_t b0, uint32_t b1)
{
    asm volatile(
        "mma.sync.aligned.m16n8k16.row.col.f32.f16.f16.f32 "
        "{%0,%1,%2,%3}, {%4,%5,%6,%7}, {%8,%9}, {%0,%1,%2,%3};"
        : "+f"(c[0]), "+f"(c[1]), "+f"(c[2]), "+f"(c[3])
        : "r"(a[0]), "r"(a[1]), "r"(a[2]), "r"(a[3]), "r"(b0), "r"(b1));
}

__device__ __forceinline__ uint32_t smem_u32c(const void* p) {
    uint32_t a;
    asm("{ .reg .u64 t; cvta.to.shared.u64 t, %1; cvt.u32.u64 %0, t; }"
        : "=r"(a) : "l"(p));
    return a;
}

// exact fp32 dot (true cosine sim) for rescore
__device__ __forceinline__ float dot32(int p, int code)
{
    const float4* xr = (const float4*)(g_xn + (size_t)p * 32);
    const float4* er = (const float4*)(g_en + (size_t)code * 32);
    float s = 0.f;
#pragma unroll
    for (int q = 0; q < 8; q++) {
        float4 x = __ldg(xr + q), e = __ldg(er + q);
        s += x.x * e.x; s += x.y * e.y; s += x.z * e.z; s += x.w * e.w;
    }
    return s;
}

// shared prologue: stage x-hi tile, extract A fragments (16 regs)
// smem layout after prologue: [0,16384) buf0, [16384,32768) buf1, [32768,34816) merge
__device__ __forceinline__ void stage_prologue(
    __half* smc, int tid, int px0, int mw, int g, int kq, uint32_t A[2][2][4])
{
    for (int i = tid; i < 512; i += 256) {
        int r = i >> 2, q = i & 3;
        ((uint4*)(smc + r * XH_STR))[q] =
            ((const uint4*)(g_xhi + (size_t)(px0 + r) * 32))[q];
    }
    __syncthreads();
#pragma unroll
    for (int kt = 0; kt < 2; kt++) {
        int k0 = kt * 16 + kq * 2;
#pragma unroll
        for (int mt = 0; mt < 2; mt++) {
            int r0 = mw * 32 + mt * 16 + g;
            A[kt][mt][0] = *(const uint32_t*)(smc + r0 * XH_STR + k0);
            A[kt][mt][1] = *(const uint32_t*)(smc + (r0 + 8) * XH_STR + k0);
            A[kt][mt][2] = *(const uint32_t*)(smc + r0 * XH_STR + k0 + 8);
            A[kt][mt][3] = *(const uint32_t*)(smc + (r0 + 8) * XH_STR + k0 + 8);
        }
    }
    __syncthreads();
}

__device__ __forceinline__ void chunk_copy_async(uint32_t dbase, const char* src, int tid)
{
#pragma unroll
    for (int j = 0; j < 4; j++) {
        uint32_t d = dbase + (tid + 256 * j) * 16;
        asm volatile("cp.async.ca.shared.global [%0], [%1], 16;"
                     :: "r"(d), "l"(src + (tid + 256 * j) * 16) : "memory");
    }
    asm volatile("cp.async.commit_group;" ::: "memory");
}

// ---------------------------------------------------------------------------
// Kernel C1 (stage 1): fp16 hi.hi approx sims, per-pixel MAX VALUE only.
// 256 thr = 4 pixel-quarter warps x 2 code-half warps; chunk 256 codes.
// ---------------------------------------------------------------------------
__global__ void __launch_bounds__(256, 2) sims_max_kernel()
{
    extern __shared__ __half smc[];

    int tid  = threadIdx.x;
    int wid  = tid >> 5;
    int lane = tid & 31;
    int g    = lane >> 2;
    int kq   = lane & 3;
    int cw   = wid >> 2;
    int mw   = wid & 3;
    int px0  = blockIdx.x * 128;
    int cbase = blockIdx.y * CPS;

    uint32_t A[2][2][4];
    stage_prologue(smc, tid, px0, mw, g, kq, A);

    uint32_t buf_base = smem_u32c(smc);
    chunk_copy_async(buf_base, (const char*)(g_ehi + (size_t)cbase * 32), tid);

    float bv[4];
#pragma unroll
    for (int s = 0; s < 4; s++) bv[s] = -3.4e38f;

    for (int ch = 0; ch < CPS; ch += CH2) {
        int cur = (ch >> 8) & 1;
        __syncthreads();
        if (ch + CH2 < CPS) {
            chunk_copy_async(buf_base + (cur ^ 1) * 16384,
                             (const char*)(g_ehi + (size_t)(cbase + ch + CH2) * 32), tid);
            asm volatile("cp.async.wait_group 1;" ::: "memory");
        } else {
            asm volatile("cp.async.wait_group 0;" ::: "memory");
        }
        __syncthreads();

        const char* ebuf = (const char*)smc + cur * 16384;

#pragma unroll
        for (int sub = 0; sub < 4; sub++) {
            const char* es = ebuf + (cw * 16 + sub * 4) * 512;

            float acc[4][2][4];
#pragma unroll
            for (int nt = 0; nt < 4; nt++)
#pragma unroll
                for (int mt = 0; mt < 2; mt++)
#pragma unroll
                    for (int c = 0; c < 4; c++) acc[nt][mt][c] = 0.f;

#pragma unroll
            for (int kt = 0; kt < 2; kt++) {
#pragma unroll
                for (int nt = 0; nt < 4; nt++) {
                    uint2 bb = *(const uint2*)(es + nt * 512 + kt * 256 + lane * 8);
                    mma16816h(acc[nt][0], A[kt][0], bb.x, bb.y);
                    mma16816h(acc[nt][1], A[kt][1], bb.x, bb.y);
                }
            }

#pragma unroll
            for (int mt = 0; mt < 2; mt++) {
#pragma unroll
                for (int h = 0; h < 2; h++) {
                    int s = mt * 2 + h;
                    float m01 = fmaxf(acc[0][mt][h * 2], acc[0][mt][h * 2 + 1]);
                    float m23 = fmaxf(acc[1][mt][h * 2], acc[1][mt][h * 2 + 1]);
                    float m45 = fmaxf(acc[2][mt][h * 2], acc[2][mt][h * 2 + 1]);
                    float m67 = fmaxf(acc[3][mt][h * 2], acc[3][mt][h * 2 + 1]);
                    bv[s] = fmaxf(bv[s], fmaxf(fmaxf(m01, m23), fmaxf(m45, m67)));
                }
            }
        }
    }

    // max over kq lanes
#pragma unroll
    for (int s = 0; s < 4; s++) {
        bv[s] = fmaxf(bv[s], __shfl_xor_sync(0xffffffffu, bv[s], 1));
        bv[s] = fmaxf(bv[s], __shfl_xor_sync(0xffffffffu, bv[s], 2));
    }
    // merge cw halves via smem
    float* sv = (float*)((char*)smc + 32768);   // [2][128]
    __syncthreads();
    if (kq == 0) {
#pragma unroll
        for (int s = 0; s < 4; s++) {
            int mt = s >> 1, h = s & 1;
            sv[cw * 128 + mw * 32 + mt * 16 + h * 8 + g] = bv[s];
        }
    }
    __syncthreads();
    if (tid < 128)
        g_pval[blockIdx.y * PIXELS + px0 + tid] = fmaxf(sv[tid], sv[128 + tid]);
}

// ---------------------------------------------------------------------------
// Kernel M: global approx max per pixel (over splits)
// ---------------------------------------------------------------------------
__global__ void amax_kernel()
{
    int p = blockIdx.x * 256 + threadIdx.x;
    float m = -3.4e38f;
#pragma unroll
    for (int s = 0; s < SPLITS; s++) m = fmaxf(m, g_pval[s * PIXELS + p]);
    g_amax[p] = m;
}

// ---------------------------------------------------------------------------
// Kernel C2 (stage 2): recompute approx sims (bit-identical), screen vs
// amax - DELTA, exact fp32 rescore for the rare candidates.
// ---------------------------------------------------------------------------
__global__ void __launch_bounds__(256, 2) sims_rescore_kernel()
{
    extern __shared__ __half smc[];

    int tid  = threadIdx.x;
    int wid  = tid >> 5;
    int lane = tid & 31;
    int g    = lane >> 2;
    int kq   = lane & 3;
    int cw   = wid >> 2;
    int mw   = wid & 3;
    int px0  = blockIdx.x * 128;
    int cbase = blockIdx.y * CPS;

    uint32_t A[2][2][4];
    stage_prologue(smc, tid, px0, mw, g, kq, A);

    // per-slot pixel + screening threshold
    int   pp[4];
    float th[4];
#pragma unroll
    for (int s = 0; s < 4; s++) {
        int mt = s >> 1, h = s & 1;
        pp[s] = px0 + mw * 32 + mt * 16 + h * 8 + g;
        th[s] = g_amax[pp[s]] - DELTA;
    }

    uint32_t buf_base = smem_u32c(smc);
    chunk_copy_async(buf_base, (const char*)(g_ehi + (size_t)cbase * 32), tid);

    float bv[4];
    int   bi[4];
#pragma unroll
    for (int s = 0; s < 4; s++) { bv[s] = -3.4e38f; bi[s] = 0x7fffffff; }

    for (int ch = 0; ch < CPS; ch += CH2) {
        int cur = (ch >> 8) & 1;
        __syncthreads();
        if (ch + CH2 < CPS) {
            chunk_copy_async(buf_base + (cur ^ 1) * 16384,
                             (const char*)(g_ehi + (size_t)(cbase + ch + CH2) * 32), tid);
            asm volatile("cp.async.wait_group 1;" ::: "memory");
        } else {
            asm volatile("cp.async.wait_group 0;" ::: "memory");
        }
        __syncthreads();

        const char* ebuf = (const char*)smc + cur * 16384;

#pragma unroll
        for (int sub = 0; sub < 4; sub++) {
            const char* es = ebuf + (cw * 16 + sub * 4) * 512;

            float acc[4][2][4];
#pragma unroll
            for (int nt = 0; nt < 4; nt++)
#pragma unroll
                for (int mt = 0; mt < 2; mt++)
#pragma unroll
                    for (int c = 0; c < 4; c++) acc[nt][mt][c] = 0.f;

#pragma unroll
            for (int kt = 0; kt < 2; kt++) {
#pragma unroll
                for (int nt = 0; nt < 4; nt++) {
                    uint2 bb = *(const uint2*)(es + nt * 512 + kt * 256 + lane * 8);
                    mma16816h(acc[nt][0], A[kt][0], bb.x, bb.y);
                    mma16816h(acc[nt][1], A[kt][1], bb.x, bb.y);
                }
            }

            int cb = cbase + ch + cw * 128 + sub * 32 + kq * 2;
#pragma unroll
            for (int mt = 0; mt < 2; mt++) {
#pragma unroll
                for (int h = 0; h < 2; h++) {
                    int s = mt * 2 + h;
                    float m01 = fmaxf(acc[0][mt][h * 2], acc[0][mt][h * 2 + 1]);
                    float m23 = fmaxf(acc[1][mt][h * 2], acc[1][mt][h * 2 + 1]);
                    float m45 = fmaxf(acc[2][mt][h * 2], acc[2][mt][h * 2 + 1]);
                    float m67 = fmaxf(acc[3][mt][h * 2], acc[3][mt][h * 2 + 1]);
                    float vm = fmaxf(fmaxf(m01, m23), fmaxf(m45, m67));
                    if (vm >= th[s]) {
                        // rare: rescore every candidate in this slot exactly
#pragma unroll
                        for (int nt = 0; nt < 4; nt++) {
#pragma unroll
                            for (int c = 0; c < 2; c++) {
                                if (acc[nt][mt][h * 2 + c] >= th[s]) {
                                    int code = cb + nt * 8 + c;
                                    float tv = dot32(pp[s], code);
                                    if (tv > bv[s] ||
                                        (tv == bv[s] && code < bi[s])) {
                                        bv[s] = tv; bi[s] = code;
                                    }
                                }
                            }
                        }
                    }
                }
            }
        }
    }

    // reduce across the 4 kq lanes (lower index wins ties)
#pragma unroll
    for (int s = 0; s < 4; s++) {
#pragma unroll
        for (int o = 1; o <= 2; o <<= 1) {
            float ov = __shfl_xor_sync(0xffffffffu, bv[s], o);
            int   oi = __shfl_xor_sync(0xffffffffu, bi[s], o);
            if (ov > bv[s] || (ov == bv[s] && oi < bi[s])) { bv[s] = ov; bi[s] = oi; }
        }
    }

    // merge the two code-half warps per pixel via smem
    float* sv = (float*)((char*)smc + 32768);   // [2][128]
    int*   si = (int*)(sv + 256);               // [2][128]
    __syncthreads();
    if (kq == 0) {
#pragma unroll
        for (int s = 0; s < 4; s++) {
            int mt = s >> 1, h = s & 1;
            int pix = mw * 32 + mt * 16 + h * 8 + g;
            sv[cw * 128 + pix] = bv[s];
            si[cw * 128 + pix] = bi[s];
        }
    }
    __syncthreads();
    if (tid < 128) {
        float v0 = sv[tid];       int i0 = si[tid];
        float v1 = sv[128 + tid]; int i1 = si[128 + tid];
        if (v1 > v0 || (v1 == v0 && i1 < i0)) { v0 = v1; i0 = i1; }
        g_pval[blockIdx.y * PIXELS + px0 + tid] = v0;
        g_pidx[blockIdx.y * PIXELS + px0 + tid] = i0;
    }
}

// ---------------------------------------------------------------------------
// Kernel F: reduce split partials -> closest; histogram; per-pixel loss partial.
// ---------------------------------------------------------------------------
__global__ void reduce_kernel(float* __restrict__ out)
{
    int p = blockIdx.x * 256 + threadIdx.x;
    float bv = -3.4e38f;
    int   bi = 0x7fffffff;
#pragma unroll
    for (int s = 0; s < SPLITS; s++) {
        float v = g_pval[s * PIXELS + p];
        int  ix = g_pidx[s * PIXELS + p];
        if (v > bv || (v == bv && ix < bi)) { bv = v; bi = ix; }
    }
    g_closest[p] = bi;
    out[CLOSEST_OFF + p] = (float)bi;
    atomicAdd(&g_hist[bi], 1);

    float s2 = 0.f;
    const float4* xr = (const float4*)(g_xn + (size_t)p * 32);
    const float4* er = (const float4*)(g_en + (size_t)bi * 32);
#pragma unroll
    for (int q = 0; q < 8; q++) {
        float4 x = xr[q], e = er[q];
        float d0 = x.x - e.x, d1 = x.y - e.y, d2 = x.z - e.z, d3 = x.w - e.w;
        s2 += d0 * d0; s2 += d1 * d1; s2 += d2 * d2; s2 += d3 * d3;
    }
    g_lossp[p] = s2;
}

// ---------------------------------------------------------------------------
// Kernel D: expansion GEMM: out[b,d,hw] = sum_f lat[p][f] * exp_w[d][f] + exp_b[d]
// ---------------------------------------------------------------------------
__global__ void expand_kernel(const float* __restrict__ ew,
                              const float* __restrict__ eb,
                              float* __restrict__ out)
{
    __shared__ float Wsh[64 * 32];
    __shared__ float bsh[64];
    int tid = threadIdx.x;
    int d0  = blockIdx.y * 64;

    const float4* src = (const float4*)(ew + (size_t)d0 * 32);
    float4* dst = (float4*)Wsh;
    dst[tid]       = src[tid];
    dst[tid + 256] = src[tid + 256];
    if (tid < 64) bsh[tid] = eb[d0 + tid];
    __syncthreads();

    int p  = blockIdx.x * 256 + tid;
    int b  = p >> 10;
    int hw = p & 1023;
    int idx = g_closest[p];

    float4 lat[8];
    const float4* lr = (const float4*)(g_en + (size_t)idx * 32);
#pragma unroll
    for (int q = 0; q < 8; q++) lat[q] = lr[q];

    float* outp = out + OUT_OFF + ((size_t)b * 512 + d0) * 1024 + hw;
#pragma unroll 2
    for (int dd = 0; dd < 64; dd++) {
        const float4* wr = (const float4*)(Wsh + dd * 32);
        float s = bsh[dd];
#pragma unroll
        for (int q = 0; q < 8; q++) {
            float4 w = wr[q];
            s += lat[q].x * w.x; s += lat[q].y * w.y;
            s += lat[q].z * w.z; s += lat[q].w * w.w;
        }
        outp[(size_t)dd * 1024] = s;
    }
}

// ---------------------------------------------------------------------------
// Kernel G: deterministic final reductions -> loss_q, perplexity
// ---------------------------------------------------------------------------
__global__ void finalize_kernel(float* __restrict__ out)
{
    __shared__ double sh[256];
    int tid = threadIdx.x;

    double ls = 0.0;
    for (int i = tid; i < PIXELS; i += 256) ls += (double)g_lossp[i];
    sh[tid] = ls;
    __syncthreads();
    for (int o = 128; o; o >>= 1) {
        if (tid < o) sh[tid] += sh[tid + o];
        __syncthreads();
    }
    double loss = sh[0] / (double)(PIXELS * 32);
    __syncthreads();

    double ps = 0.0;
    for (int i = tid; i < NN; i += 256) {
        float u = (float)g_hist[i] * (1.0f / 8192.0f);
        ps += -(double)u * log((double)u + 1e-6);
    }
    sh[tid] = ps;
    __syncthreads();
    for (int o = 128; o; o >>= 1) {
        if (tid < o) sh[tid] += sh[tid + o];
        __syncthreads();
    }
    if (tid == 0) {
        out[LOSS_OFF] = (float)loss;
        out[PERP_OFF] = (float)exp(sh[0]);
    }
}

// ---------------------------------------------------------------------------
extern "C" void kernel_launch(void* const* d_in, const int* in_sizes, int n_in,
                              void* d_out, int out_size)
{
    const float* enc = (const float*)d_in[0];  // [8,512,32,32]
    const float* emb = (const float*)d_in[1];  // [16384,32]
    const float* pw  = (const float*)d_in[2];  // [32,512]
    const float* pb  = (const float*)d_in[3];  // [32]
    const float* ew  = (const float*)d_in[4];  // [512,32]
    const float* eb  = (const float*)d_in[5];  // [512]
    float* out = (float*)d_out;

    (void)in_sizes; (void)n_in; (void)out_size;

    const int a_smem = (FF * DD + 32 * 33 + 32) * (int)sizeof(float); // 69888
    cudaFuncSetAttribute(proj_norm_kernel,
                         cudaFuncAttributeMaxDynamicSharedMemorySize, a_smem);

    const int c_smem = 34816;  // 2x16KB chunk buffers + 2KB merge
    cudaFuncSetAttribute(sims_max_kernel,
                         cudaFuncAttributeMaxDynamicSharedMemorySize, c_smem);
    cudaFuncSetAttribute(sims_rescore_kernel,
                         cudaFuncAttributeMaxDynamicSharedMemorySize, c_smem);

    proj_norm_kernel<<<256, 256, a_smem>>>(enc, pw, pb);
    enorm_kernel<<<2048, 256>>>(emb);
    sims_max_kernel<<<dim3(64, SPLITS), 256, c_smem>>>();
    amax_kernel<<<32, 256>>>();
    sims_rescore_kernel<<<dim3(64, SPLITS), 256, c_smem>>>();
    reduce_kernel<<<32, 256>>>(out);
    expand_kernel<<<dim3(32, 8), 256>>>(ew, eb, out);
    finalize_kernel<<<1, 256>>>(out);
}